// round 1
// baseline (speedup 1.0000x reference)
#include <cuda_runtime.h>
#include <math.h>

// Problem constants
#define B_ 8
#define S_ 2048
#define D_ 1024
#define H_ 1024
#define L_ 4
#define M_ (B_ * S_)   // 16384 rows
#define N_ (2 * H_)    // 2048 cols (gate|hidden)
#define K_ 1024        // inner dim (D or H)

// Scratch (allocation-free rule: __device__ globals)
__device__ float g_gh[(size_t)M_ * N_];    // per-layer pre-activation (B,S,2H)
__device__ float g_inp[(size_t)M_ * H_];   // current layer input / residual stream

// ---------------------------------------------------------------------------
// GEMM: g_gh = A @ W^T + bias
// A: [M_, K_] row-major, W: [N_, K_] row-major (both K-contiguous -> NT gemm)
// ---------------------------------------------------------------------------
#define BM 128
#define BN 128
#define BK 16
#define PAD 4

__global__ __launch_bounds__(256, 2) void gemm_nt(const float* __restrict__ A,
                                                  const float* __restrict__ W,
                                                  const float* __restrict__ bias) {
    __shared__ float As[BK][BM + PAD];
    __shared__ float Bs[BK][BN + PAD];

    const int tid = threadIdx.x;
    const int rowBase = blockIdx.y * BM;
    const int colBase = blockIdx.x * BN;
    const int tx = tid & 15;   // 16 col-threads
    const int ty = tid >> 4;   // 16 row-threads

    float acc[8][8];
#pragma unroll
    for (int i = 0; i < 8; ++i)
#pragma unroll
        for (int j = 0; j < 8; ++j) acc[i][j] = 0.f;

    for (int k0 = 0; k0 < K_; k0 += BK) {
        // Load 128x16 A-tile and 128x16 W-tile, store transposed [k][m]
#pragma unroll
        for (int it = 0; it < 2; ++it) {
            int f = tid + it * 256;          // 0..511 float4 slots
            int r = f >> 2;                  // row within tile
            int c = (f & 3) << 2;            // k-offset within tile
            float4 va = *(const float4*)(A + (size_t)(rowBase + r) * K_ + k0 + c);
            As[c + 0][r] = va.x; As[c + 1][r] = va.y;
            As[c + 2][r] = va.z; As[c + 3][r] = va.w;
            float4 vb = *(const float4*)(W + (size_t)(colBase + r) * K_ + k0 + c);
            Bs[c + 0][r] = vb.x; Bs[c + 1][r] = vb.y;
            Bs[c + 2][r] = vb.z; Bs[c + 3][r] = vb.w;
        }
        __syncthreads();

#pragma unroll
        for (int k = 0; k < BK; ++k) {
            float a[8], b[8];
            *(float4*)&a[0] = *(const float4*)&As[k][ty * 8];
            *(float4*)&a[4] = *(const float4*)&As[k][ty * 8 + 4];
            *(float4*)&b[0] = *(const float4*)&Bs[k][tx * 8];
            *(float4*)&b[4] = *(const float4*)&Bs[k][tx * 8 + 4];
#pragma unroll
            for (int i = 0; i < 8; ++i)
#pragma unroll
                for (int j = 0; j < 8; ++j) acc[i][j] = fmaf(a[i], b[j], acc[i][j]);
        }
        __syncthreads();
    }

#pragma unroll
    for (int i = 0; i < 8; ++i) {
        int row = rowBase + ty * 8 + i;
#pragma unroll
        for (int j = 0; j < 8; j += 4) {
            int col = colBase + tx * 8 + j;
            float4 v;
            v.x = acc[i][j + 0] + bias[col + 0];
            v.y = acc[i][j + 1] + bias[col + 1];
            v.z = acc[i][j + 2] + bias[col + 2];
            v.w = acc[i][j + 3] + bias[col + 3];
            *(float4*)(g_gh + (size_t)row * N_ + col) = v;
        }
    }
}

// ---------------------------------------------------------------------------
// Log-space minGRU scan + residual. One thread per (b, h) channel.
//   log_h_t = logaddexp( log(1-z_t) + log_h_{t-1}, log z_t + log g(hidden_t) )
//   out_t   = exp(log_h_t) + resid_t
//   finals  = exp(log_h_{S-1})  (pre-residual)
// ---------------------------------------------------------------------------
__device__ __forceinline__ float softplus_f(float x) {
    // max(x,0) + log1p(exp(-|x|)) : numerically stable
    return fmaxf(x, 0.f) + log1pf(__expf(-fabsf(x)));
}
__device__ __forceinline__ float log_g_f(float x) {
    return (x >= 0.f) ? __logf(x + 0.5f) : -softplus_f(-x);
}

__global__ void scan_kernel(const float* __restrict__ resid,
                            float* __restrict__ outp,
                            float* __restrict__ finals,
                            const float* __restrict__ h0) {
    int t = blockIdx.x * blockDim.x + threadIdx.x;   // 0..8191
    int b = t >> 10;
    int hid = t & 1023;

    float log_h = log_g_f(h0[t]);

    const float* ghp = g_gh + (size_t)b * S_ * N_ + hid;
    const float* rp  = resid + (size_t)b * S_ * H_ + hid;
    float*       op  = outp  + (size_t)b * S_ * H_ + hid;

    float hval = 0.f;
    for (int s = 0; s < S_; ++s) {
        float g  = ghp[(size_t)s * N_];
        float hd = ghp[(size_t)s * N_ + H_];
        float lc  = -softplus_f(g);                      // log(1 - z)
        float lzv = -softplus_f(-g) + log_g_f(hd);       // log z + log g(h~)

        float a = lc + log_h;
        float m = fmaxf(a, lzv);
        log_h = m + log1pf(__expf(fminf(a, lzv) - m));
        hval = __expf(log_h);

        op[(size_t)s * H_] = hval + rp[(size_t)s * H_];
    }
    finals[t] = hval;
}

// ---------------------------------------------------------------------------
// Launcher
// Inputs (metadata order): x(B,S,D), h(L,B,1,H), W0(2H,D), b0(2H),
//                          Wl(L-1,2H,H), bl(L-1,2H)
// Output: out(B,S,H) flattened, then finals(L,B,1,H)
// ---------------------------------------------------------------------------
extern "C" void kernel_launch(void* const* d_in, const int* in_sizes, int n_in,
                              void* d_out, int out_size) {
    const float* x  = (const float*)d_in[0];
    const float* h  = (const float*)d_in[1];
    const float* W0 = (const float*)d_in[2];
    const float* b0 = (const float*)d_in[3];
    const float* Wl = (const float*)d_in[4];
    const float* bl = (const float*)d_in[5];

    float* out    = (float*)d_out;
    float* finals = out + (size_t)M_ * H_;

    float* inp_buf = nullptr;
    cudaGetSymbolAddress((void**)&inp_buf, g_inp);

    dim3 ggrid(N_ / BN, M_ / BM);   // (16, 128)

    // Layer 0: input = x
    gemm_nt<<<ggrid, 256>>>(x, W0, b0);
    scan_kernel<<<64, 128>>>(x, inp_buf, finals, h);

    // Layers 1..3: input = inp_buf (in-place residual stream)
    for (int l = 1; l < L_; ++l) {
        gemm_nt<<<ggrid, 256>>>(inp_buf,
                                Wl + (size_t)(l - 1) * N_ * H_,
                                bl + (size_t)(l - 1) * N_);
        float* ob = (l == L_ - 1) ? out : inp_buf;
        scan_kernel<<<64, 128>>>(inp_buf, ob,
                                 finals + (size_t)l * B_ * H_,
                                 h + (size_t)l * B_ * H_);
    }
}

// round 3
// speedup vs baseline: 1.4491x; 1.4491x over previous
#include <cuda_runtime.h>
#include <cuda_bf16.h>
#include <math.h>
#include <stdint.h>

// ---------------- problem constants ----------------
#define B_  8
#define S_  2048
#define HID 1024
#define L_  4
#define M_  (B_ * S_)    // 16384
#define N_  (2 * HID)    // 2048
#define K_  1024

// ---------------- GEMM tiling ----------------
#define BM 128
#define BN 256
#define BK 64            // bf16 elems per iter (128 bytes per row)
#define NT 48            // 3 passes * 16 k-chunks
#define STAGES 3
#define GTHREADS 512

#define STAGE_BYTES (49152)          // 16KB A + 32KB B
#define SM_A(s) ((s) * STAGE_BYTES)
#define SM_B(s) ((s) * STAGE_BYTES + 16384)
#define SMEM_BYTES (STAGES * STAGE_BYTES)   // 144KB

// ---------------- scratch (allocation-free rule) ----------------
__device__ float         g_gh[(size_t)M_ * N_];
__device__ float         g_inp[(size_t)M_ * HID];
__device__ __nv_bfloat16 g_Ahi[(size_t)M_ * K_];
__device__ __nv_bfloat16 g_Alo[(size_t)M_ * K_];
__device__ __nv_bfloat16 g_Whi[(size_t)N_ * K_];
__device__ __nv_bfloat16 g_Wlo[(size_t)N_ * K_];

// ---------------- helpers ----------------
__device__ __forceinline__ uint32_t smem_u32(const void* p) {
    uint32_t a;
    asm("{ .reg .u64 t; cvta.to.shared.u64 t, %1; cvt.u32.u64 %0, t; }"
        : "=r"(a) : "l"(p));
    return a;
}

__device__ __forceinline__ void cp16(uint32_t dst, const void* src) {
    asm volatile("cp.async.cg.shared.global [%0], [%1], 16;"
                 :: "r"(dst), "l"(src) : "memory");
}
#define CP_COMMIT() asm volatile("cp.async.commit_group;" ::: "memory")
#define CP_WAIT1()  asm volatile("cp.async.wait_group 1;" ::: "memory")

__device__ __forceinline__ void ldm_x4(uint32_t* r, uint32_t addr) {
    asm volatile("ldmatrix.sync.aligned.m8n8.x4.shared.b16 {%0,%1,%2,%3}, [%4];"
                 : "=r"(r[0]), "=r"(r[1]), "=r"(r[2]), "=r"(r[3]) : "r"(addr));
}

__device__ __forceinline__ void mma_16816(float* c, const uint32_t* a,
                                          const uint32_t* b) {
    asm volatile(
        "mma.sync.aligned.m16n8k16.row.col.f32.bf16.bf16.f32 "
        "{%0,%1,%2,%3}, {%4,%5,%6,%7}, {%8,%9}, {%0,%1,%2,%3};"
        : "+f"(c[0]), "+f"(c[1]), "+f"(c[2]), "+f"(c[3])
        : "r"(a[0]), "r"(a[1]), "r"(a[2]), "r"(a[3]), "r"(b[0]), "r"(b[1]));
}

// ---------------------------------------------------------------------------
// mma.sync bf16 GEMM with split-bf16 3-pass accumulation:
//   gh[M,N] = Ahi@Whi^T + Alo@Whi^T + Ahi@Wlo^T + bias
// grid = (N_/BN, M_/BM) = (8, 128), 512 threads, 144KB dyn smem
// ---------------------------------------------------------------------------
__global__ void __launch_bounds__(GTHREADS, 1)
gemm_mma(const __nv_bfloat16* __restrict__ Ahi, const __nv_bfloat16* __restrict__ Alo,
         const __nv_bfloat16* __restrict__ Whi, const __nv_bfloat16* __restrict__ Wlo,
         const float* __restrict__ bias, float* __restrict__ out) {
    extern __shared__ char smem[];
    const uint32_t sb = smem_u32(smem);
    const int tid = threadIdx.x;
    const int wid = tid >> 5, lid = tid & 31;
    const int wr = wid & 1;          // warp row: 64 rows each
    const int wc = wid >> 1;         // warp col: 0..7, 32 cols each
    const int rowBase = blockIdx.y * BM;
    const int colBase = blockIdx.x * BN;

    float acc[4][4][4];
#pragma unroll
    for (int i = 0; i < 4; ++i)
#pragma unroll
        for (int j = 0; j < 4; ++j)
#pragma unroll
            for (int k = 0; k < 4; ++k) acc[i][j][k] = 0.f;

    // per-lane ldmatrix geometry
    const int a_r  = (lid & 7) + ((lid >> 3) & 1) * 8;   // row within m16 tile
    const int a_kb = lid >> 4;                           // which k8 block
    const int b_r  = (lid & 7) + ((lid >> 4) & 1) * 8;   // row within n16 pair
    const int b_kb = (lid >> 3) & 1;

    // ---- copy one BK chunk into stage s ----
    auto copy_chunk = [&](int kt, int s) {
        const int pass = kt >> 4;
        const int kc = kt & 15;
        const __nv_bfloat16* Ap = (pass == 1) ? Alo : Ahi;
        const __nv_bfloat16* Bp = (pass == 2) ? Wlo : Whi;
#pragma unroll
        for (int i = 0; i < 2; ++i) {            // A: 1024 chunks of 16B
            int c = tid + i * GTHREADS;
            int r = c >> 3, u = c & 7;
            const void* src = Ap + (size_t)(rowBase + r) * K_ + kc * 64 + u * 8;
            cp16(sb + SM_A(s) + r * 128 + ((u ^ (r & 7)) << 4), src);
        }
#pragma unroll
        for (int i = 0; i < 4; ++i) {            // B: 2048 chunks of 16B
            int c = tid + i * GTHREADS;
            int r = c >> 3, u = c & 7;
            const void* src = Bp + (size_t)(colBase + r) * K_ + kc * 64 + u * 8;
            cp16(sb + SM_B(s) + r * 128 + ((u ^ (r & 7)) << 4), src);
        }
    };

    copy_chunk(0, 0); CP_COMMIT();
    copy_chunk(1, 1); CP_COMMIT();

    for (int kt = 0; kt < NT; ++kt) {
        const int s = kt % STAGES;
        CP_WAIT1();
        __syncthreads();
        if (kt + 2 < NT) copy_chunk(kt + 2, (kt + 2) % STAGES);
        CP_COMMIT();

        // compute on stage s: 4 k16-steps
#pragma unroll
        for (int ks = 0; ks < 4; ++ks) {
            uint32_t af[4][4], bf[2][4];
#pragma unroll
            for (int mt = 0; mt < 4; ++mt) {
                int r = wr * 64 + mt * 16 + a_r;
                int u = ks * 2 + a_kb;
                ldm_x4(af[mt], sb + SM_A(s) + r * 128 + ((u ^ (r & 7)) << 4));
            }
#pragma unroll
            for (int np = 0; np < 2; ++np) {
                int n = wc * 32 + np * 16 + b_r;
                int u = ks * 2 + b_kb;
                ldm_x4(bf[np], sb + SM_B(s) + n * 128 + ((u ^ (n & 7)) << 4));
            }
#pragma unroll
            for (int mt = 0; mt < 4; ++mt) {
#pragma unroll
                for (int nt = 0; nt < 4; ++nt) {
                    // bf[nt/2] regs: {b0 even tile, b1 even, b0 odd, b1 odd}
                    uint32_t bb[2] = { bf[nt >> 1][(nt & 1) * 2],
                                       bf[nt >> 1][(nt & 1) * 2 + 1] };
                    mma_16816(acc[mt][nt], af[mt], bb);
                }
            }
        }
        __syncthreads();
    }

    // ---- epilogue: bias add + fp32 store ----
    const int g = lid >> 2, tig = lid & 3;
#pragma unroll
    for (int mt = 0; mt < 4; ++mt) {
        int row0 = rowBase + wr * 64 + mt * 16 + g;
#pragma unroll
        for (int nt = 0; nt < 4; ++nt) {
            int col = colBase + wc * 32 + nt * 8 + tig * 2;
            float b0 = bias[col], b1 = bias[col + 1];
            float2 v0 = { acc[mt][nt][0] + b0, acc[mt][nt][1] + b1 };
            float2 v1 = { acc[mt][nt][2] + b0, acc[mt][nt][3] + b1 };
            *(float2*)(out + (size_t)row0 * N_ + col) = v0;
            *(float2*)(out + (size_t)(row0 + 8) * N_ + col) = v1;
        }
    }
}

// ---------------------------------------------------------------------------
// fp32 -> (bf16 hi, bf16 lo) split conversion
// ---------------------------------------------------------------------------
__global__ void conv_split(const float* __restrict__ in,
                           __nv_bfloat16* __restrict__ hi,
                           __nv_bfloat16* __restrict__ lo, int n4) {
    int i = blockIdx.x * blockDim.x + threadIdx.x;
    if (i >= n4) return;
    float4 v = ((const float4*)in)[i];
    __nv_bfloat16 h0 = __float2bfloat16(v.x);
    __nv_bfloat16 h1 = __float2bfloat16(v.y);
    __nv_bfloat16 h2 = __float2bfloat16(v.z);
    __nv_bfloat16 h3 = __float2bfloat16(v.w);
    __nv_bfloat16 l0 = __float2bfloat16(v.x - __bfloat162float(h0));
    __nv_bfloat16 l1 = __float2bfloat16(v.y - __bfloat162float(h1));
    __nv_bfloat16 l2 = __float2bfloat16(v.z - __bfloat162float(h2));
    __nv_bfloat16 l3 = __float2bfloat16(v.w - __bfloat162float(h3));
    ((__nv_bfloat162*)hi)[i * 2 + 0] = __nv_bfloat162(h0, h1);
    ((__nv_bfloat162*)hi)[i * 2 + 1] = __nv_bfloat162(h2, h3);
    ((__nv_bfloat162*)lo)[i * 2 + 0] = __nv_bfloat162(l0, l1);
    ((__nv_bfloat162*)lo)[i * 2 + 1] = __nv_bfloat162(l2, l3);
}

// ---------------------------------------------------------------------------
// Log-space minGRU scan + residual. One thread per (b, h) channel.
// ---------------------------------------------------------------------------
__device__ __forceinline__ float softplus_f(float x) {
    return fmaxf(x, 0.f) + log1pf(__expf(-fabsf(x)));
}
__device__ __forceinline__ float log_g_f(float x) {
    return (x >= 0.f) ? __logf(x + 0.5f) : -softplus_f(-x);
}

__global__ void scan_kernel(const float* __restrict__ resid,
                            float* __restrict__ outp,
                            float* __restrict__ finals,
                            const float* __restrict__ h0) {
    int t = blockIdx.x * blockDim.x + threadIdx.x;   // 0..8191
    int b = t >> 10;
    int hid = t & 1023;

    float log_h = log_g_f(h0[t]);

    const float* ghp = g_gh + (size_t)b * S_ * N_ + hid;
    const float* rp  = resid + (size_t)b * S_ * HID + hid;
    float*       op  = outp  + (size_t)b * S_ * HID + hid;

    float hval = 0.f;
    for (int s = 0; s < S_; ++s) {
        float g  = ghp[(size_t)s * N_];
        float hd = ghp[(size_t)s * N_ + HID];
        float lc  = -softplus_f(g);
        float lzv = -softplus_f(-g) + log_g_f(hd);

        float a = lc + log_h;
        float m = fmaxf(a, lzv);
        log_h = m + log1pf(__expf(fminf(a, lzv) - m));
        hval = __expf(log_h);

        op[(size_t)s * HID] = hval + rp[(size_t)s * HID];
    }
    finals[t] = hval;
}

// ---------------------------------------------------------------------------
// Launcher
// ---------------------------------------------------------------------------
extern "C" void kernel_launch(void* const* d_in, const int* in_sizes, int n_in,
                              void* d_out, int out_size) {
    const float* x  = (const float*)d_in[0];
    const float* h  = (const float*)d_in[1];
    const float* W0 = (const float*)d_in[2];
    const float* b0 = (const float*)d_in[3];
    const float* Wl = (const float*)d_in[4];
    const float* bl = (const float*)d_in[5];

    float* out    = (float*)d_out;
    float* finals = out + (size_t)M_ * HID;

    float *gh, *inp;
    __nv_bfloat16 *Ahi, *Alo, *Whi, *Wlo;
    cudaGetSymbolAddress((void**)&gh,  g_gh);
    cudaGetSymbolAddress((void**)&inp, g_inp);
    cudaGetSymbolAddress((void**)&Ahi, g_Ahi);
    cudaGetSymbolAddress((void**)&Alo, g_Alo);
    cudaGetSymbolAddress((void**)&Whi, g_Whi);
    cudaGetSymbolAddress((void**)&Wlo, g_Wlo);

    cudaFuncSetAttribute(gemm_mma, cudaFuncAttributeMaxDynamicSharedMemorySize,
                         SMEM_BYTES);

    const int nA4 = M_ * K_ / 4;
    const int nW4 = N_ * K_ / 4;
    dim3 ggrid(N_ / BN, M_ / BM);   // (8, 128)

    for (int l = 0; l < L_; ++l) {
        const float* src = (l == 0) ? x : inp;
        const float* W   = (l == 0) ? W0 : (Wl + (size_t)(l - 1) * N_ * K_);
        const float* b   = (l == 0) ? b0 : (bl + (size_t)(l - 1) * N_);

        conv_split<<<(nA4 + 255) / 256, 256>>>(src, Ahi, Alo, nA4);
        conv_split<<<(nW4 + 255) / 256, 256>>>(W, Whi, Wlo, nW4);
        gemm_mma<<<ggrid, GTHREADS, SMEM_BYTES>>>(Ahi, Alo, Whi, Wlo, b, gh);

        float* ob = (l == L_ - 1) ? out : inp;
        scan_kernel<<<256, 32>>>(src, ob, finals + (size_t)l * B_ * HID,
                                 h + (size_t)l * B_ * HID);
    }
}

// round 6
// speedup vs baseline: 1.5930x; 1.0992x over previous
#include <cuda_runtime.h>
#include <cuda_fp16.h>
#include <math.h>
#include <stdint.h>

// ---------------- problem constants ----------------
#define B_  8
#define S_  2048
#define HID 1024
#define L_  4
#define M_  (B_ * S_)    // 16384
#define N_  (2 * HID)    // 2048
#define K_  1024

// ---------------- GEMM tiling ----------------
#define BM 128
#define BN 256
#define BK 64            // fp16 elems per chunk = 128 B per row
#define NCHUNK 16        // K_/BK
#define STAGES 3
#define GTHREADS 512

// stage = Ah(16KB) + Al(16KB) + B(32KB) = 64KB
#define STAGE_BYTES 65536
#define OFF_AH 0
#define OFF_AL 16384
#define OFF_B  32768
#define SMEM_BYTES (1024 + STAGES * STAGE_BYTES)   // 197632

#define A_TILE_B 16384   // 128x64 fp16
#define W_TILE_B 32768   // 256x64 fp16

// ---------------- scratch (allocation-free rule) ----------------
__device__ float g_gh[(size_t)M_ * N_];
__device__ float g_inp[(size_t)M_ * HID];
__device__ uint4 g_Ahi[(size_t)M_ * K_ / 8];   // tiled+swizzled fp16
__device__ uint4 g_Alo[(size_t)M_ * K_ / 8];
__device__ uint4 g_Whi[(size_t)N_ * K_ / 8];

// ---------------- helpers ----------------
__device__ __forceinline__ uint32_t smem_u32(const void* p) {
    uint32_t a;
    asm("{ .reg .u64 t; cvta.to.shared.u64 t, %1; cvt.u32.u64 %0, t; }"
        : "=r"(a) : "l"(p));
    return a;
}
__device__ __forceinline__ void bulk_g2s(uint32_t dst, const void* src,
                                         uint32_t bytes, uint32_t mbar) {
    asm volatile(
        "cp.async.bulk.shared::cta.global.mbarrier::complete_tx::bytes "
        "[%0], [%1], %2, [%3];"
        :: "r"(dst), "l"(src), "r"(bytes), "r"(mbar) : "memory");
}
#define MBAR_INIT(a, c) \
    asm volatile("mbarrier.init.shared.b64 [%0], %1;" :: "r"(a), "r"((uint32_t)(c)) : "memory")
#define MBAR_EXPECT(a, b) \
    asm volatile("mbarrier.arrive.expect_tx.shared.b64 _, [%0], %1;" \
                 :: "r"(a), "r"((uint32_t)(b)) : "memory")
#define MBAR_WAIT(a, ph) do {                                                    \
    asm volatile(                                                                 \
        "{ .reg .pred P;\n"                                                       \
        "LAB_%=: mbarrier.try_wait.parity.acquire.cta.shared::cta.b64 P, [%0], %1, 0x989680;\n" \
        "@P bra.uni DONE_%=;\n"                                                   \
        "bra.uni LAB_%=;\n"                                                       \
        "DONE_%=: }"                                                              \
        :: "r"(a), "r"((uint32_t)(ph)) : "memory");                               \
} while (0)

__device__ __forceinline__ void ldm_x4(uint32_t* r, uint32_t addr) {
    asm volatile("ldmatrix.sync.aligned.m8n8.x4.shared.b16 {%0,%1,%2,%3}, [%4];"
                 : "=r"(r[0]), "=r"(r[1]), "=r"(r[2]), "=r"(r[3]) : "r"(addr));
}
__device__ __forceinline__ void mma_16816(float* c, const uint32_t* a,
                                          const uint32_t* b) {
    asm volatile(
        "mma.sync.aligned.m16n8k16.row.col.f32.f16.f16.f32 "
        "{%0,%1,%2,%3}, {%4,%5,%6,%7}, {%8,%9}, {%0,%1,%2,%3};"
        : "+f"(c[0]), "+f"(c[1]), "+f"(c[2]), "+f"(c[3])
        : "r"(a[0]), "r"(a[1]), "r"(a[2]), "r"(a[3]), "r"(b[0]), "r"(b[1]));
}

// ---------------------------------------------------------------------------
// fp16 GEMM, 2-pass split-A: gh = (Ah + Al) @ Wh^T + bias
// grid (N_/BN=8, M_/BM=128), 512 threads, bulk-copy pipeline
// ---------------------------------------------------------------------------
__global__ void __launch_bounds__(GTHREADS, 1)
gemm_mma(const char* __restrict__ Ahi, const char* __restrict__ Alo,
         const char* __restrict__ Whi,
         const float* __restrict__ bias, float* __restrict__ out) {
    extern __shared__ __align__(1024) char smem[];
    const uint32_t sb = smem_u32(smem);
    const int tid = threadIdx.x;
    const int wid = tid >> 5, lid = tid & 31;
    const int wr = wid & 1;          // 2 x 64 rows
    const int wc = wid >> 1;         // 8 x 32 cols
    const int rowBase = blockIdx.y * BM;
    const int colBase = blockIdx.x * BN;

    if (tid == 0) {
        MBAR_INIT(sb + 0, 1);
        MBAR_INIT(sb + 8, 1);
        MBAR_INIT(sb + 16, 1);
    }
    __syncthreads();

    auto issue = [&](int kc, int s) {
        uint32_t bar = sb + s * 8;
        uint32_t st = sb + 1024 + s * STAGE_BYTES;
        MBAR_EXPECT(bar, STAGE_BYTES);
        bulk_g2s(st + OFF_AH, Ahi + ((size_t)blockIdx.y * NCHUNK + kc) * A_TILE_B,
                 A_TILE_B, bar);
        bulk_g2s(st + OFF_AL, Alo + ((size_t)blockIdx.y * NCHUNK + kc) * A_TILE_B,
                 A_TILE_B, bar);
        bulk_g2s(st + OFF_B,  Whi + ((size_t)blockIdx.x * NCHUNK + kc) * W_TILE_B,
                 W_TILE_B, bar);
    };

    if (tid == 0) { issue(0, 0); issue(1, 1); }

    float acc[4][4][4];
#pragma unroll
    for (int i = 0; i < 4; ++i)
#pragma unroll
        for (int j = 0; j < 4; ++j)
#pragma unroll
            for (int k = 0; k < 4; ++k) acc[i][j][k] = 0.f;

    // ldmatrix lane geometry
    const int a_r  = (lid & 7) + ((lid >> 3) & 1) * 8;
    const int a_kb = lid >> 4;
    const int b_r  = (lid & 7) + ((lid >> 4) & 1) * 8;
    const int b_kb = (lid >> 3) & 1;

    int ph[3] = {0, 0, 0};

    for (int kt = 0; kt < NCHUNK; ++kt) {
        const int s = kt % STAGES;
        MBAR_WAIT(sb + s * 8, ph[s]);
        ph[s] ^= 1;
        if (tid == 0 && kt + 2 < NCHUNK) issue(kt + 2, (kt + 2) % STAGES);

        const uint32_t st = sb + 1024 + s * STAGE_BYTES;
#pragma unroll
        for (int pass = 0; pass < 2; ++pass) {
            const uint32_t aBase = st + (pass ? OFF_AL : OFF_AH);
#pragma unroll
            for (int ks = 0; ks < 4; ++ks) {
                uint32_t af[4][4], bf[2][4];
#pragma unroll
                for (int mt = 0; mt < 4; ++mt) {
                    int r = wr * 64 + mt * 16 + a_r;
                    int u = ks * 2 + a_kb;
                    ldm_x4(af[mt], aBase + r * 128 + ((u ^ (r & 7)) << 4));
                }
#pragma unroll
                for (int np = 0; np < 2; ++np) {
                    int n = wc * 32 + np * 16 + b_r;
                    int u = ks * 2 + b_kb;
                    ldm_x4(bf[np], st + OFF_B + n * 128 + ((u ^ (n & 7)) << 4));
                }
#pragma unroll
                for (int mt = 0; mt < 4; ++mt)
#pragma unroll
                    for (int nt = 0; nt < 4; ++nt) {
                        uint32_t bb[2] = { bf[nt >> 1][(nt & 1) * 2],
                                           bf[nt >> 1][(nt & 1) * 2 + 1] };
                        mma_16816(acc[mt][nt], af[mt], bb);
                    }
            }
        }
        __syncthreads();
    }

    // epilogue: bias + fp32 store
    const int g = lid >> 2, tig = lid & 3;
#pragma unroll
    for (int mt = 0; mt < 4; ++mt) {
        int row0 = rowBase + wr * 64 + mt * 16 + g;
#pragma unroll
        for (int nt = 0; nt < 4; ++nt) {
            int col = colBase + wc * 32 + nt * 8 + tig * 2;
            float b0 = bias[col], b1 = bias[col + 1];
            float2 v0 = { acc[mt][nt][0] + b0, acc[mt][nt][1] + b1 };
            float2 v1 = { acc[mt][nt][2] + b0, acc[mt][nt][3] + b1 };
            *(float2*)(out + (size_t)row0 * N_ + col) = v0;
            *(float2*)(out + (size_t)(row0 + 8) * N_ + col) = v1;
        }
    }
}

// ---------------------------------------------------------------------------
// fp32 -> fp16 hi/lo, written tiled [rows/TR][16][TR][64] with XOR swizzle.
// One thread = one 16B unit (8 values).
// ---------------------------------------------------------------------------
template <int TR, bool SPLIT>
__global__ void conv_tiled(const float* __restrict__ in,
                           uint4* __restrict__ hi, uint4* __restrict__ lo,
                           int nunits) {
    int i = blockIdx.x * blockDim.x + threadIdx.x;
    if (i >= nunits) return;
    int m  = i >> 7;          // row (K/8 = 128 units per row)
    int ku = i & 127;
    int kc = ku >> 3, u = ku & 7;
    int mb = m / TR, r = m % TR;

    const float4* p = (const float4*)(in + (size_t)m * K_ + ku * 8);
    float4 v0 = p[0], v1 = p[1];
    float vv[8] = {v0.x, v0.y, v0.z, v0.w, v1.x, v1.y, v1.z, v1.w};

    uint32_t hw[4], lw[4];
#pragma unroll
    for (int j = 0; j < 4; ++j) {
        __half h0 = __float2half_rn(vv[2 * j]);
        __half h1 = __float2half_rn(vv[2 * j + 1]);
        hw[j] = (uint32_t)__half_as_ushort(h0) |
                ((uint32_t)__half_as_ushort(h1) << 16);
        if (SPLIT) {
            __half l0 = __float2half_rn(vv[2 * j] - __half2float(h0));
            __half l1 = __float2half_rn(vv[2 * j + 1] - __half2float(h1));
            lw[j] = (uint32_t)__half_as_ushort(l0) |
                    ((uint32_t)__half_as_ushort(l1) << 16);
        }
    }
    size_t tile = ((size_t)mb * NCHUNK + kc) * (TR * 8);   // uint4 units
    size_t off = tile + r * 8 + (u ^ (r & 7));
    hi[off] = make_uint4(hw[0], hw[1], hw[2], hw[3]);
    if (SPLIT) lo[off] = make_uint4(lw[0], lw[1], lw[2], lw[3]);
}

// ---------------------------------------------------------------------------
// Log-space minGRU scan + residual. One thread per (b, h) channel.
// ---------------------------------------------------------------------------
__device__ __forceinline__ float softplus_f(float x) {
    return fmaxf(x, 0.f) + log1pf(__expf(-fabsf(x)));
}
__device__ __forceinline__ float log_g_f(float x) {
    return (x >= 0.f) ? __logf(x + 0.5f) : -softplus_f(-x);
}

__global__ void scan_kernel(const float* __restrict__ resid,
                            float* __restrict__ outp,
                            float* __restrict__ finals,
                            const float* __restrict__ h0) {
    int t = blockIdx.x * blockDim.x + threadIdx.x;   // 0..8191
    int b = t >> 10;
    int hid = t & 1023;

    float log_h = log_g_f(h0[t]);

    const float* ghp = g_gh + (size_t)b * S_ * N_ + hid;
    const float* rp  = resid + (size_t)b * S_ * HID + hid;
    float*       op  = outp  + (size_t)b * S_ * HID + hid;

    float hval = 0.f;
    for (int s = 0; s < S_; ++s) {
        float g  = ghp[(size_t)s * N_];
        float hd = ghp[(size_t)s * N_ + HID];
        float lc  = -softplus_f(g);
        float lzv = -softplus_f(-g) + log_g_f(hd);

        float a = lc + log_h;
        float m = fmaxf(a, lzv);
        log_h = m + log1pf(__expf(fminf(a, lzv) - m));
        hval = __expf(log_h);

        op[(size_t)s * HID] = hval + rp[(size_t)s * HID];
    }
    finals[t] = hval;
}

// ---------------------------------------------------------------------------
// Launcher
// ---------------------------------------------------------------------------
extern "C" void kernel_launch(void* const* d_in, const int* in_sizes, int n_in,
                              void* d_out, int out_size) {
    const float* x  = (const float*)d_in[0];
    const float* h  = (const float*)d_in[1];
    const float* W0 = (const float*)d_in[2];
    const float* b0 = (const float*)d_in[3];
    const float* Wl = (const float*)d_in[4];
    const float* bl = (const float*)d_in[5];

    float* out    = (float*)d_out;
    float* finals = out + (size_t)M_ * HID;

    float *gh, *inp;
    uint4 *Ahi, *Alo, *Whi;
    cudaGetSymbolAddress((void**)&gh,  g_gh);
    cudaGetSymbolAddress((void**)&inp, g_inp);
    cudaGetSymbolAddress((void**)&Ahi, g_Ahi);
    cudaGetSymbolAddress((void**)&Alo, g_Alo);
    cudaGetSymbolAddress((void**)&Whi, g_Whi);

    cudaFuncSetAttribute(gemm_mma, cudaFuncAttributeMaxDynamicSharedMemorySize,
                         SMEM_BYTES);

    const int nAu = M_ * K_ / 8;   // 2M units
    const int nWu = N_ * K_ / 8;   // 256K units
    dim3 ggrid(N_ / BN, M_ / BM);  // (8, 128)

    for (int l = 0; l < L_; ++l) {
        const float* src = (l == 0) ? x : inp;
        const float* W   = (l == 0) ? W0 : (Wl + (size_t)(l - 1) * N_ * K_);
        const float* b   = (l == 0) ? b0 : (bl + (size_t)(l - 1) * N_);

        conv_tiled<BM, true><<<(nAu + 255) / 256, 256>>>(src, Ahi, Alo, nAu);
        conv_tiled<BN, false><<<(nWu + 255) / 256, 256>>>(W, Whi, nullptr, nWu);
        gemm_mma<<<ggrid, GTHREADS, SMEM_BYTES>>>((const char*)Ahi,
                                                  (const char*)Alo,
                                                  (const char*)Whi, b, gh);

        float* ob = (l == L_ - 1) ? out : inp;
        scan_kernel<<<64, 128>>>(src, ob, finals + (size_t)l * B_ * HID,
                                 h + (size_t)l * B_ * HID);
    }
}

// round 7
// speedup vs baseline: 1.7260x; 1.0835x over previous
#include <cuda_runtime.h>
#include <cuda_fp16.h>
#include <math.h>
#include <stdint.h>

// ---------------- problem constants ----------------
#define B_  8
#define S_  2048
#define HID 1024
#define L_  4
#define M_  (B_ * S_)    // 16384
#define N_  (2 * HID)    // 2048
#define K_  1024

// ---------------- GEMM tiling ----------------
#define BM 128
#define BN 256
#define BK 64            // fp16 elems per chunk = 128 B per row
#define NCHUNK 16        // K_/BK
#define STAGES 4
#define GTHREADS 512

// stage = A(16KB) + B(32KB) = 48KB
#define STAGE_BYTES 49152
#define OFF_A 0
#define OFF_B 16384
#define SMEM_BYTES (1024 + STAGES * STAGE_BYTES)   // 197632

#define A_TILE_B 16384   // 128x64 fp16
#define W_TILE_B 32768   // 256x64 fp16

// ---------------- scratch (allocation-free rule) ----------------
__device__ float g_gh[(size_t)M_ * N_];
__device__ float g_inp[(size_t)M_ * HID];
__device__ uint4 g_Ah[(size_t)M_ * K_ / 8];   // tiled+swizzled fp16
__device__ uint4 g_Wh[(size_t)N_ * K_ / 8];

// ---------------- helpers ----------------
__device__ __forceinline__ uint32_t smem_u32(const void* p) {
    uint32_t a;
    asm("{ .reg .u64 t; cvta.to.shared.u64 t, %1; cvt.u32.u64 %0, t; }"
        : "=r"(a) : "l"(p));
    return a;
}
__device__ __forceinline__ void bulk_g2s(uint32_t dst, const void* src,
                                         uint32_t bytes, uint32_t mbar) {
    asm volatile(
        "cp.async.bulk.shared::cta.global.mbarrier::complete_tx::bytes "
        "[%0], [%1], %2, [%3];"
        :: "r"(dst), "l"(src), "r"(bytes), "r"(mbar) : "memory");
}
#define MBAR_INIT(a, c) \
    asm volatile("mbarrier.init.shared.b64 [%0], %1;" :: "r"(a), "r"((uint32_t)(c)) : "memory")
#define MBAR_EXPECT(a, b) \
    asm volatile("mbarrier.arrive.expect_tx.shared.b64 _, [%0], %1;" \
                 :: "r"(a), "r"((uint32_t)(b)) : "memory")
#define MBAR_WAIT(a, ph) do {                                                    \
    asm volatile(                                                                 \
        "{ .reg .pred P;\n"                                                       \
        "LAB_%=: mbarrier.try_wait.parity.acquire.cta.shared::cta.b64 P, [%0], %1, 0x989680;\n" \
        "@P bra.uni DONE_%=;\n"                                                   \
        "bra.uni LAB_%=;\n"                                                       \
        "DONE_%=: }"                                                              \
        :: "r"(a), "r"((uint32_t)(ph)) : "memory");                               \
} while (0)

__device__ __forceinline__ void ldm_x4(uint32_t* r, uint32_t addr) {
    asm volatile("ldmatrix.sync.aligned.m8n8.x4.shared.b16 {%0,%1,%2,%3}, [%4];"
                 : "=r"(r[0]), "=r"(r[1]), "=r"(r[2]), "=r"(r[3]) : "r"(addr));
}
__device__ __forceinline__ void mma_16816(float* c, const uint32_t* a,
                                          const uint32_t* b) {
    asm volatile(
        "mma.sync.aligned.m16n8k16.row.col.f32.f16.f16.f32 "
        "{%0,%1,%2,%3}, {%4,%5,%6,%7}, {%8,%9}, {%0,%1,%2,%3};"
        : "+f"(c[0]), "+f"(c[1]), "+f"(c[2]), "+f"(c[3])
        : "r"(a[0]), "r"(a[1]), "r"(a[2]), "r"(a[3]), "r"(b[0]), "r"(b[1]));
}

// ---------------------------------------------------------------------------
// fp16 GEMM (single pass): gh = A @ W^T + bias
// grid (N_/BN=8, M_/BM=128), 512 threads, 4-stage bulk-copy pipeline
// ---------------------------------------------------------------------------
__global__ void __launch_bounds__(GTHREADS, 1)
gemm_mma(const char* __restrict__ Ah, const char* __restrict__ Wh,
         const float* __restrict__ bias, float* __restrict__ out) {
    extern __shared__ __align__(1024) char smem[];
    const uint32_t sb = smem_u32(smem);
    const int tid = threadIdx.x;
    const int wid = tid >> 5, lid = tid & 31;
    const int wr = wid & 1;          // 2 x 64 rows
    const int wc = wid >> 1;         // 8 x 32 cols
    const int rowBase = blockIdx.y * BM;
    const int colBase = blockIdx.x * BN;

    if (tid == 0) {
#pragma unroll
        for (int s = 0; s < STAGES; ++s) MBAR_INIT(sb + s * 8, 1);
    }
    __syncthreads();

    auto issue = [&](int kc, int s) {
        uint32_t bar = sb + s * 8;
        uint32_t st = sb + 1024 + s * STAGE_BYTES;
        MBAR_EXPECT(bar, STAGE_BYTES);
        bulk_g2s(st + OFF_A, Ah + ((size_t)blockIdx.y * NCHUNK + kc) * A_TILE_B,
                 A_TILE_B, bar);
        bulk_g2s(st + OFF_B, Wh + ((size_t)blockIdx.x * NCHUNK + kc) * W_TILE_B,
                 W_TILE_B, bar);
    };

    if (tid == 0) { issue(0, 0); issue(1, 1); issue(2, 2); }

    float acc[4][4][4];
#pragma unroll
    for (int i = 0; i < 4; ++i)
#pragma unroll
        for (int j = 0; j < 4; ++j)
#pragma unroll
            for (int k = 0; k < 4; ++k) acc[i][j][k] = 0.f;

    // ldmatrix lane geometry
    const int a_r  = (lid & 7) + ((lid >> 3) & 1) * 8;
    const int a_kb = lid >> 4;
    const int b_r  = (lid & 7) + ((lid >> 4) & 1) * 8;
    const int b_kb = (lid >> 3) & 1;

    int ph[STAGES] = {0, 0, 0, 0};

    for (int kt = 0; kt < NCHUNK; ++kt) {
        const int s = kt % STAGES;
        MBAR_WAIT(sb + s * 8, ph[s]);
        ph[s] ^= 1;
        if (tid == 0 && kt + 3 < NCHUNK) issue(kt + 3, (kt + 3) % STAGES);

        const uint32_t st = sb + 1024 + s * STAGE_BYTES;
#pragma unroll
        for (int ks = 0; ks < 4; ++ks) {
            uint32_t af[4][4], bf[2][4];
#pragma unroll
            for (int mt = 0; mt < 4; ++mt) {
                int r = wr * 64 + mt * 16 + a_r;
                int u = ks * 2 + a_kb;
                ldm_x4(af[mt], st + OFF_A + r * 128 + ((u ^ (r & 7)) << 4));
            }
#pragma unroll
            for (int np = 0; np < 2; ++np) {
                int n = wc * 32 + np * 16 + b_r;
                int u = ks * 2 + b_kb;
                ldm_x4(bf[np], st + OFF_B + n * 128 + ((u ^ (n & 7)) << 4));
            }
#pragma unroll
            for (int mt = 0; mt < 4; ++mt)
#pragma unroll
                for (int nt = 0; nt < 4; ++nt) {
                    uint32_t bb[2] = { bf[nt >> 1][(nt & 1) * 2],
                                       bf[nt >> 1][(nt & 1) * 2 + 1] };
                    mma_16816(acc[mt][nt], af[mt], bb);
                }
        }
        __syncthreads();
    }

    // epilogue: bias + fp32 store
    const int g = lid >> 2, tig = lid & 3;
#pragma unroll
    for (int mt = 0; mt < 4; ++mt) {
        int row0 = rowBase + wr * 64 + mt * 16 + g;
#pragma unroll
        for (int nt = 0; nt < 4; ++nt) {
            int col = colBase + wc * 32 + nt * 8 + tig * 2;
            float b0 = bias[col], b1 = bias[col + 1];
            float2 v0 = { acc[mt][nt][0] + b0, acc[mt][nt][1] + b1 };
            float2 v1 = { acc[mt][nt][2] + b0, acc[mt][nt][3] + b1 };
            *(float2*)(out + (size_t)row0 * N_ + col) = v0;
            *(float2*)(out + (size_t)(row0 + 8) * N_ + col) = v1;
        }
    }
}

// ---------------------------------------------------------------------------
// fp32 -> fp16, written tiled [rows/TR][16][TR][64] with XOR swizzle.
// One thread = one 16B output unit (8 values).
// ---------------------------------------------------------------------------
template <int TR>
__global__ void conv_tiled(const float* __restrict__ in,
                           uint4* __restrict__ hi, int nunits) {
    int i = blockIdx.x * blockDim.x + threadIdx.x;
    if (i >= nunits) return;
    int m  = i >> 7;          // row (K/8 = 128 units per row)
    int ku = i & 127;
    int kc = ku >> 3, u = ku & 7;
    int mb = m / TR, r = m % TR;

    const float4* p = (const float4*)(in + (size_t)m * K_ + ku * 8);
    float4 v0 = p[0], v1 = p[1];
    float vv[8] = {v0.x, v0.y, v0.z, v0.w, v1.x, v1.y, v1.z, v1.w};

    uint32_t hw[4];
#pragma unroll
    for (int j = 0; j < 4; ++j) {
        __half h0 = __float2half_rn(vv[2 * j]);
        __half h1 = __float2half_rn(vv[2 * j + 1]);
        hw[j] = (uint32_t)__half_as_ushort(h0) |
                ((uint32_t)__half_as_ushort(h1) << 16);
    }
    size_t tile = ((size_t)mb * NCHUNK + kc) * (TR * 8);   // uint4 units
    hi[tile + r * 8 + (u ^ (r & 7))] = make_uint4(hw[0], hw[1], hw[2], hw[3]);
}

// ---------------------------------------------------------------------------
// Log-space minGRU scan + residual. One thread per (b, h) channel.
// ---------------------------------------------------------------------------
__device__ __forceinline__ float softplus_f(float x) {
    return fmaxf(x, 0.f) + log1pf(__expf(-fabsf(x)));
}
__device__ __forceinline__ float log_g_f(float x) {
    return (x >= 0.f) ? __logf(x + 0.5f) : -softplus_f(-x);
}

__global__ void scan_kernel(const float* __restrict__ resid,
                            float* __restrict__ outp,
                            float* __restrict__ finals,
                            const float* __restrict__ h0) {
    int t = blockIdx.x * blockDim.x + threadIdx.x;   // 0..8191
    int b = t >> 10;
    int hid = t & 1023;

    float log_h = log_g_f(h0[t]);

    const float* ghp = g_gh + (size_t)b * S_ * N_ + hid;
    const float* rp  = resid + (size_t)b * S_ * HID + hid;
    float*       op  = outp  + (size_t)b * S_ * HID + hid;

    float hval = 0.f;
    for (int s = 0; s < S_; ++s) {
        float g  = ghp[(size_t)s * N_];
        float hd = ghp[(size_t)s * N_ + HID];
        float lc  = -softplus_f(g);
        float lzv = -softplus_f(-g) + log_g_f(hd);

        float a = lc + log_h;
        float m = fmaxf(a, lzv);
        log_h = m + log1pf(__expf(fminf(a, lzv) - m));
        hval = __expf(log_h);

        op[(size_t)s * HID] = hval + rp[(size_t)s * HID];
    }
    finals[t] = hval;
}

// ---------------------------------------------------------------------------
// Launcher
// ---------------------------------------------------------------------------
extern "C" void kernel_launch(void* const* d_in, const int* in_sizes, int n_in,
                              void* d_out, int out_size) {
    const float* x  = (const float*)d_in[0];
    const float* h  = (const float*)d_in[1];
    const float* W0 = (const float*)d_in[2];
    const float* b0 = (const float*)d_in[3];
    const float* Wl = (const float*)d_in[4];
    const float* bl = (const float*)d_in[5];

    float* out    = (float*)d_out;
    float* finals = out + (size_t)M_ * HID;

    float *gh, *inp;
    uint4 *Ah, *Wh;
    cudaGetSymbolAddress((void**)&gh,  g_gh);
    cudaGetSymbolAddress((void**)&inp, g_inp);
    cudaGetSymbolAddress((void**)&Ah,  g_Ah);
    cudaGetSymbolAddress((void**)&Wh,  g_Wh);

    cudaFuncSetAttribute(gemm_mma, cudaFuncAttributeMaxDynamicSharedMemorySize,
                         SMEM_BYTES);

    const int nAu = M_ * K_ / 8;   // 2M units
    const int nWu = N_ * K_ / 8;   // 256K units
    dim3 ggrid(N_ / BN, M_ / BM);  // (8, 128)

    for (int l = 0; l < L_; ++l) {
        const float* src = (l == 0) ? x : inp;
        const float* W   = (l == 0) ? W0 : (Wl + (size_t)(l - 1) * N_ * K_);
        const float* b   = (l == 0) ? b0 : (bl + (size_t)(l - 1) * N_);

        conv_tiled<BM><<<(nAu + 255) / 256, 256>>>(src, Ah, nAu);
        conv_tiled<BN><<<(nWu + 255) / 256, 256>>>(W, Wh, nWu);
        gemm_mma<<<ggrid, GTHREADS, SMEM_BYTES>>>((const char*)Ah,
                                                  (const char*)Wh, b, gh);

        float* ob = (l == L_ - 1) ? out : inp;
        scan_kernel<<<64, 128>>>(src, ob, finals + (size_t)l * B_ * HID,
                                 h + (size_t)l * B_ * HID);
    }
}

// round 9
// speedup vs baseline: 9.7103x; 5.6260x over previous
#include <cuda_runtime.h>
#include <cuda_fp16.h>
#include <math.h>
#include <stdint.h>

// ---------------- problem constants ----------------
#define B_  8
#define S_  2048
#define HID 1024
#define L_  4
#define M_  (B_ * S_)    // 16384
#define N_  (2 * HID)    // 2048
#define K_  1024
#define CH_ 8192         // B*H channels
#define NCK 32           // scan chunks
#define CKS 64           // steps per chunk

// ---------------- GEMM tiling ----------------
#define BM 128
#define BN 256
#define NCHUNK 16        // K_/64
#define STAGES 4
#define GTHREADS 512

#define STAGE_BYTES 49152
#define OFF_A 0
#define OFF_B 16384
#define SMEM_BYTES (1024 + STAGES * STAGE_BYTES)

#define A_TILE_B 16384   // 128x64 fp16
#define W_TILE_B 32768   // 256x64 fp16

// ---------------- scratch (allocation-free rule) ----------------
__device__ float g_gh[(size_t)M_ * N_];
__device__ float g_inp[(size_t)M_ * HID];
__device__ float g_a[(size_t)M_ * HID];
__device__ float g_b[(size_t)M_ * HID];
__device__ float g_sumA[CH_ * NCK];
__device__ float g_sumB[CH_ * NCK];
__device__ float g_start[CH_ * NCK];
__device__ uint4 g_Ah[(size_t)M_ * K_ / 8];
__device__ uint4 g_Wh[(size_t)N_ * K_ / 8];

// ---------------- helpers ----------------
__device__ __forceinline__ uint32_t smem_u32(const void* p) {
    uint32_t a;
    asm("{ .reg .u64 t; cvta.to.shared.u64 t, %1; cvt.u32.u64 %0, t; }"
        : "=r"(a) : "l"(p));
    return a;
}
__device__ __forceinline__ void bulk_g2s(uint32_t dst, const void* src,
                                         uint32_t bytes, uint32_t mbar) {
    asm volatile(
        "cp.async.bulk.shared::cta.global.mbarrier::complete_tx::bytes "
        "[%0], [%1], %2, [%3];"
        :: "r"(dst), "l"(src), "r"(bytes), "r"(mbar) : "memory");
}
#define MBAR_INIT(a, c) \
    asm volatile("mbarrier.init.shared.b64 [%0], %1;" :: "r"(a), "r"((uint32_t)(c)) : "memory")
#define MBAR_EXPECT(a, b) \
    asm volatile("mbarrier.arrive.expect_tx.shared.b64 _, [%0], %1;" \
                 :: "r"(a), "r"((uint32_t)(b)) : "memory")
#define MBAR_WAIT(a, ph) do {                                                    \
    asm volatile(                                                                 \
        "{ .reg .pred P;\n"                                                       \
        "LAB_%=: mbarrier.try_wait.parity.acquire.cta.shared::cta.b64 P, [%0], %1, 0x989680;\n" \
        "@P bra.uni DONE_%=;\n"                                                   \
        "bra.uni LAB_%=;\n"                                                       \
        "DONE_%=: }"                                                              \
        :: "r"(a), "r"((uint32_t)(ph)) : "memory");                               \
} while (0)

__device__ __forceinline__ void ldm_x4(uint32_t* r, uint32_t addr) {
    asm volatile("ldmatrix.sync.aligned.m8n8.x4.shared.b16 {%0,%1,%2,%3}, [%4];"
                 : "=r"(r[0]), "=r"(r[1]), "=r"(r[2]), "=r"(r[3]) : "r"(addr));
}
__device__ __forceinline__ void mma_16816(float* c, const uint32_t* a,
                                          const uint32_t* b) {
    asm volatile(
        "mma.sync.aligned.m16n8k16.row.col.f32.f16.f16.f32 "
        "{%0,%1,%2,%3}, {%4,%5,%6,%7}, {%8,%9}, {%0,%1,%2,%3};"
        : "+f"(c[0]), "+f"(c[1]), "+f"(c[2]), "+f"(c[3])
        : "r"(a[0]), "r"(a[1]), "r"(a[2]), "r"(a[3]), "r"(b[0]), "r"(b[1]));
}

// ---------------------------------------------------------------------------
// fp16 GEMM: gh = A @ W^T + bias
// ---------------------------------------------------------------------------
__global__ void __launch_bounds__(GTHREADS, 1)
gemm_mma(const char* __restrict__ Ah, const char* __restrict__ Wh,
         const float* __restrict__ bias, float* __restrict__ out) {
    extern __shared__ __align__(1024) char smem[];
    const uint32_t sb = smem_u32(smem);
    const int tid = threadIdx.x;
    const int wid = tid >> 5, lid = tid & 31;
    const int wr = wid & 1;
    const int wc = wid >> 1;
    const int rowBase = blockIdx.y * BM;
    const int colBase = blockIdx.x * BN;

    if (tid == 0) {
#pragma unroll
        for (int s = 0; s < STAGES; ++s) MBAR_INIT(sb + s * 8, 1);
    }
    __syncthreads();

    auto issue = [&](int kc, int s) {
        uint32_t bar = sb + s * 8;
        uint32_t st = sb + 1024 + s * STAGE_BYTES;
        MBAR_EXPECT(bar, STAGE_BYTES);
        bulk_g2s(st + OFF_A, Ah + ((size_t)blockIdx.y * NCHUNK + kc) * A_TILE_B,
                 A_TILE_B, bar);
        bulk_g2s(st + OFF_B, Wh + ((size_t)blockIdx.x * NCHUNK + kc) * W_TILE_B,
                 W_TILE_B, bar);
    };

    if (tid == 0) { issue(0, 0); issue(1, 1); issue(2, 2); }

    float acc[4][4][4];
#pragma unroll
    for (int i = 0; i < 4; ++i)
#pragma unroll
        for (int j = 0; j < 4; ++j)
#pragma unroll
            for (int k = 0; k < 4; ++k) acc[i][j][k] = 0.f;

    const int a_r  = (lid & 7) + ((lid >> 3) & 1) * 8;
    const int a_kb = lid >> 4;
    const int b_r  = (lid & 7) + ((lid >> 4) & 1) * 8;
    const int b_kb = (lid >> 3) & 1;

    int ph[STAGES] = {0, 0, 0, 0};

    for (int kt = 0; kt < NCHUNK; ++kt) {
        const int s = kt % STAGES;
        MBAR_WAIT(sb + s * 8, ph[s]);
        ph[s] ^= 1;
        if (tid == 0 && kt + 3 < NCHUNK) issue(kt + 3, (kt + 3) % STAGES);

        const uint32_t st = sb + 1024 + s * STAGE_BYTES;
#pragma unroll
        for (int ks = 0; ks < 4; ++ks) {
            uint32_t af[4][4], bf[2][4];
#pragma unroll
            for (int mt = 0; mt < 4; ++mt) {
                int r = wr * 64 + mt * 16 + a_r;
                int u = ks * 2 + a_kb;
                ldm_x4(af[mt], st + OFF_A + r * 128 + ((u ^ (r & 7)) << 4));
            }
#pragma unroll
            for (int np = 0; np < 2; ++np) {
                int n = wc * 32 + np * 16 + b_r;
                int u = ks * 2 + b_kb;
                ldm_x4(bf[np], st + OFF_B + n * 128 + ((u ^ (n & 7)) << 4));
            }
#pragma unroll
            for (int mt = 0; mt < 4; ++mt)
#pragma unroll
                for (int nt = 0; nt < 4; ++nt) {
                    uint32_t bb[2] = { bf[nt >> 1][(nt & 1) * 2],
                                       bf[nt >> 1][(nt & 1) * 2 + 1] };
                    mma_16816(acc[mt][nt], af[mt], bb);
                }
        }
        __syncthreads();
    }

    const int g = lid >> 2, tig = lid & 3;
#pragma unroll
    for (int mt = 0; mt < 4; ++mt) {
        int row0 = rowBase + wr * 64 + mt * 16 + g;
#pragma unroll
        for (int nt = 0; nt < 4; ++nt) {
            int col = colBase + wc * 32 + nt * 8 + tig * 2;
            float b0 = bias[col], b1 = bias[col + 1];
            float2 v0 = { acc[mt][nt][0] + b0, acc[mt][nt][1] + b1 };
            float2 v1 = { acc[mt][nt][2] + b0, acc[mt][nt][3] + b1 };
            *(float2*)(out + (size_t)row0 * N_ + col) = v0;
            *(float2*)(out + (size_t)(row0 + 8) * N_ + col) = v1;
        }
    }
}

// ---------------------------------------------------------------------------
// fp32 -> fp16 tiled+swizzled
// ---------------------------------------------------------------------------
template <int TR>
__global__ void conv_tiled(const float* __restrict__ in,
                           uint4* __restrict__ hi, int nunits) {
    int i = blockIdx.x * blockDim.x + threadIdx.x;
    if (i >= nunits) return;
    int m  = i >> 7;
    int ku = i & 127;
    int kc = ku >> 3, u = ku & 7;
    int mb = m / TR, r = m % TR;

    const float4* p = (const float4*)(in + (size_t)m * K_ + ku * 8);
    float4 v0 = p[0], v1 = p[1];
    float vv[8] = {v0.x, v0.y, v0.z, v0.w, v1.x, v1.y, v1.z, v1.w};

    uint32_t hw[4];
#pragma unroll
    for (int j = 0; j < 4; ++j) {
        __half h0 = __float2half_rn(vv[2 * j]);
        __half h1 = __float2half_rn(vv[2 * j + 1]);
        hw[j] = (uint32_t)__half_as_ushort(h0) |
                ((uint32_t)__half_as_ushort(h1) << 16);
    }
    size_t tile = ((size_t)mb * NCHUNK + kc) * (TR * 8);
    hi[tile + r * 8 + (u ^ (r & 7))] = make_uint4(hw[0], hw[1], hw[2], hw[3]);
}

// ---------------------------------------------------------------------------
// Scan phase 1: gh -> (a,b) planes + per-chunk (A,B) summaries.
//   a = sigma(-g) = 1/(1+e^g)
//   b = sigma(g) * gg(hd),  gg = hd>=0 ? hd+0.5 : sigma(hd)=e2/(1+e2)
// Shared-RCP: rr = 1/((1+e1)(1+e2)); a = rr*d2; sigma(hd) = e2*rr*d1.
// ---------------------------------------------------------------------------
__global__ void __launch_bounds__(128) scan_phase1() {
    const int ch = blockIdx.x * 128 + threadIdx.x;
    const int ck = blockIdx.y;
    const int b = ch >> 10, hid = ch & 1023;
    const size_t rowbase = (size_t)b * S_ + ck * CKS;

    const float* gh = g_gh;
    float A = 1.f, Bc = 0.f;
#pragma unroll 4
    for (int s = 0; s < CKS; ++s) {
        size_t r = rowbase + s;
        float g  = gh[r * N_ + hid];
        float hd = gh[r * N_ + HID + hid];
        float e1 = __expf(fminf(g, 60.f));
        float e2 = __expf(fminf(hd, 0.f));
        float d1 = 1.f + e1, d2 = 1.f + e2;
        float rr = __fdividef(1.f, d1 * d2);
        float a  = rr * d2;            // sigma(-g)
        float s2 = e2 * rr * d1;       // sigma(hd) = e2/(1+e2)  [hd<0 path]
        float z  = 1.f - a;            // sigma(g)
        float gg = (hd >= 0.f) ? (hd + 0.5f) : s2;
        float bv = z * gg;
        g_a[r * HID + hid] = a;
        g_b[r * HID + hid] = bv;
        Bc = fmaf(a, Bc, bv);
        A *= a;
    }
    g_sumA[ch * NCK + ck] = A;
    g_sumB[ch * NCK + ck] = Bc;
}

// ---------------------------------------------------------------------------
// Scan phase 2: per-channel warp scan over 32 chunk summaries.
// ---------------------------------------------------------------------------
__global__ void __launch_bounds__(256) scan_phase2(const float* __restrict__ h0) {
    const int gt = blockIdx.x * 256 + threadIdx.x;
    const int ch = gt >> 5;
    const int lane = gt & 31;

    float A = g_sumA[ch * NCK + lane];
    float Bv = g_sumB[ch * NCK + lane];
#pragma unroll
    for (int off = 1; off < 32; off <<= 1) {
        float pA = __shfl_up_sync(0xFFFFFFFF, A, off);
        float pB = __shfl_up_sync(0xFFFFFFFF, Bv, off);
        if (lane >= off) {
            Bv = fmaf(A, pB, Bv);
            A  = pA * A;
        }
    }
    float eA = __shfl_up_sync(0xFFFFFFFF, A, 1);
    float eB = __shfl_up_sync(0xFFFFFFFF, Bv, 1);
    if (lane == 0) { eA = 1.f; eB = 0.f; }

    float x = h0[ch];
    float h0g = (x >= 0.f) ? (x + 0.5f)
                           : __fdividef(__expf(x), 1.f + __expf(x));
    g_start[lane * CH_ + ch] = fmaf(eA, h0g, eB);
}

// ---------------------------------------------------------------------------
// Scan phase 3: local FMA scan + residual + finals.
// ---------------------------------------------------------------------------
__global__ void __launch_bounds__(128)
scan_phase3(const float* __restrict__ resid, float* __restrict__ outp,
            float* __restrict__ finals) {
    const int ch = blockIdx.x * 128 + threadIdx.x;
    const int ck = blockIdx.y;
    const int b = ch >> 10, hid = ch & 1023;
    const size_t rowbase = (size_t)b * S_ + ck * CKS;

    float h = g_start[ck * CH_ + ch];
#pragma unroll 4
    for (int s = 0; s < CKS; ++s) {
        size_t idx = (rowbase + s) * HID + hid;
        h = fmaf(g_a[idx], h, g_b[idx]);
        outp[idx] = h + resid[idx];
    }
    if (ck == NCK - 1) finals[ch] = h;
}

// ---------------------------------------------------------------------------
// Launcher
// ---------------------------------------------------------------------------
extern "C" void kernel_launch(void* const* d_in, const int* in_sizes, int n_in,
                              void* d_out, int out_size) {
    const float* x  = (const float*)d_in[0];
    const float* h  = (const float*)d_in[1];
    const float* W0 = (const float*)d_in[2];
    const float* b0 = (const float*)d_in[3];
    const float* Wl = (const float*)d_in[4];
    const float* bl = (const float*)d_in[5];

    float* out    = (float*)d_out;
    float* finals = out + (size_t)M_ * HID;

    float *gh, *inp;
    uint4 *Ah, *Wh;
    cudaGetSymbolAddress((void**)&gh,  g_gh);
    cudaGetSymbolAddress((void**)&inp, g_inp);
    cudaGetSymbolAddress((void**)&Ah,  g_Ah);
    cudaGetSymbolAddress((void**)&Wh,  g_Wh);

    cudaFuncSetAttribute(gemm_mma, cudaFuncAttributeMaxDynamicSharedMemorySize,
                         SMEM_BYTES);

    const int nAu = M_ * K_ / 8;
    const int nWu = N_ * K_ / 8;
    dim3 ggrid(N_ / BN, M_ / BM);     // (8, 128)
    dim3 sgrid(CH_ / 128, NCK);       // (64, 32)

    for (int l = 0; l < L_; ++l) {
        const float* src = (l == 0) ? x : inp;
        const float* W   = (l == 0) ? W0 : (Wl + (size_t)(l - 1) * N_ * K_);
        const float* b   = (l == 0) ? b0 : (bl + (size_t)(l - 1) * N_);

        conv_tiled<BM><<<(nAu + 255) / 256, 256>>>(src, Ah, nAu);
        conv_tiled<BN><<<(nWu + 255) / 256, 256>>>(W, Wh, nWu);
        gemm_mma<<<ggrid, GTHREADS, SMEM_BYTES>>>((const char*)Ah,
                                                  (const char*)Wh, b, gh);

        scan_phase1<<<sgrid, 128>>>();
        scan_phase2<<<CH_ * 32 / 256, 256>>>(h + (size_t)l * CH_);
        float* ob = (l == L_ - 1) ? out : inp;
        scan_phase3<<<sgrid, 128>>>(src, ob, finals + (size_t)l * CH_);
    }
}

// round 11
// speedup vs baseline: 11.1756x; 1.1509x over previous
#include <cuda_runtime.h>
#include <cuda_fp16.h>
#include <math.h>
#include <stdint.h>

// ---------------- problem constants ----------------
#define B_  8
#define S_  2048
#define HID 1024
#define L_  4
#define M_  (B_ * S_)    // 16384
#define N_  (2 * HID)    // 2048
#define K_  1024
#define CH_ 8192         // B*H channels
#define NCK 32           // scan chunks
#define CKS 64           // steps per chunk

// ---------------- GEMM tiling ----------------
#define BM 128
#define BN 256
#define NCHUNK 16        // K_/64
#define STAGES 4
#define GTHREADS 512

#define STAGE_BYTES 49152
#define OFF_A 0
#define OFF_B 16384
#define SMEM_BYTES (1024 + STAGES * STAGE_BYTES)

#define A_TILE_B 16384   // 128x64 fp16
#define W_TILE_B 32768   // 256x64 fp16

// ---------------- scratch (allocation-free rule) ----------------
__device__ uint32_t g_ab[(size_t)M_ * HID];   // packed half2 (a, b)
__device__ float    g_inp[(size_t)M_ * HID];
__device__ float    g_sumA[CH_ * NCK];
__device__ float    g_sumB[CH_ * NCK];
__device__ float    g_start[CH_ * NCK];
__device__ uint4    g_Ah[(size_t)M_ * K_ / 8];
__device__ uint4    g_Wh[(size_t)N_ * K_ / 8];

// ---------------- helpers ----------------
__device__ __forceinline__ uint32_t smem_u32(const void* p) {
    uint32_t a;
    asm("{ .reg .u64 t; cvta.to.shared.u64 t, %1; cvt.u32.u64 %0, t; }"
        : "=r"(a) : "l"(p));
    return a;
}
__device__ __forceinline__ void bulk_g2s(uint32_t dst, const void* src,
                                         uint32_t bytes, uint32_t mbar) {
    asm volatile(
        "cp.async.bulk.shared::cta.global.mbarrier::complete_tx::bytes "
        "[%0], [%1], %2, [%3];"
        :: "r"(dst), "l"(src), "r"(bytes), "r"(mbar) : "memory");
}
#define MBAR_INIT(a, c) \
    asm volatile("mbarrier.init.shared.b64 [%0], %1;" :: "r"(a), "r"((uint32_t)(c)) : "memory")
#define MBAR_EXPECT(a, b) \
    asm volatile("mbarrier.arrive.expect_tx.shared.b64 _, [%0], %1;" \
                 :: "r"(a), "r"((uint32_t)(b)) : "memory")
#define MBAR_WAIT(a, ph) do {                                                    \
    asm volatile(                                                                 \
        "{ .reg .pred P;\n"                                                       \
        "LAB_%=: mbarrier.try_wait.parity.acquire.cta.shared::cta.b64 P, [%0], %1, 0x989680;\n" \
        "@P bra.uni DONE_%=;\n"                                                   \
        "bra.uni LAB_%=;\n"                                                       \
        "DONE_%=: }"                                                              \
        :: "r"(a), "r"((uint32_t)(ph)) : "memory");                               \
} while (0)

__device__ __forceinline__ void ldm_x4(uint32_t* r, uint32_t addr) {
    asm volatile("ldmatrix.sync.aligned.m8n8.x4.shared.b16 {%0,%1,%2,%3}, [%4];"
                 : "=r"(r[0]), "=r"(r[1]), "=r"(r[2]), "=r"(r[3]) : "r"(addr));
}
__device__ __forceinline__ void mma_16816(float* c, const uint32_t* a,
                                          const uint32_t* b) {
    asm volatile(
        "mma.sync.aligned.m16n8k16.row.col.f32.f16.f16.f32 "
        "{%0,%1,%2,%3}, {%4,%5,%6,%7}, {%8,%9}, {%0,%1,%2,%3};"
        : "+f"(c[0]), "+f"(c[1]), "+f"(c[2]), "+f"(c[3])
        : "r"(a[0]), "r"(a[1]), "r"(a[2]), "r"(a[3]), "r"(b[0]), "r"(b[1]));
}

// gate/hidden pair -> packed half2 (a, b)
__device__ __forceinline__ uint32_t gate2ab(float gate, float hd) {
    float e1 = __expf(fminf(gate, 60.f));
    float e2 = __expf(fminf(hd, 0.f));
    float d1 = 1.f + e1, d2 = 1.f + e2;
    float rr = __fdividef(1.f, d1 * d2);
    float a  = rr * d2;            // sigma(-gate)
    float s2 = e2 * rr * d1;       // sigma(hd)  [hd<0 path]
    float z  = 1.f - a;            // sigma(gate)
    float gg = (hd >= 0.f) ? (hd + 0.5f) : s2;
    float bv = z * gg;
    __half2 h2 = __floats2half2_rn(a, bv);
    return *(uint32_t*)&h2;
}

// ---------------------------------------------------------------------------
// fp16 GEMM with fused gate transform: ab[m][p] = f(A@W^T + bias)
// W rows are pre-interleaved: output col 2p = gate_p, col 2p+1 = hidden_p
// ---------------------------------------------------------------------------
__global__ void __launch_bounds__(GTHREADS, 1)
gemm_mma(const char* __restrict__ Ah, const char* __restrict__ Wh,
         const float* __restrict__ bias, uint32_t* __restrict__ ab) {
    extern __shared__ __align__(1024) char smem[];
    const uint32_t sb = smem_u32(smem);
    const int tid = threadIdx.x;
    const int wid = tid >> 5, lid = tid & 31;
    const int wr = wid & 1;
    const int wc = wid >> 1;
    const int rowBase = blockIdx.y * BM;
    const int colBase = blockIdx.x * BN;

    if (tid == 0) {
#pragma unroll
        for (int s = 0; s < STAGES; ++s) MBAR_INIT(sb + s * 8, 1);
    }
    __syncthreads();

    auto issue = [&](int kc, int s) {
        uint32_t bar = sb + s * 8;
        uint32_t st = sb + 1024 + s * STAGE_BYTES;
        MBAR_EXPECT(bar, STAGE_BYTES);
        bulk_g2s(st + OFF_A, Ah + ((size_t)blockIdx.y * NCHUNK + kc) * A_TILE_B,
                 A_TILE_B, bar);
        bulk_g2s(st + OFF_B, Wh + ((size_t)blockIdx.x * NCHUNK + kc) * W_TILE_B,
                 W_TILE_B, bar);
    };

    if (tid == 0) { issue(0, 0); issue(1, 1); issue(2, 2); }

    float acc[4][4][4];
#pragma unroll
    for (int i = 0; i < 4; ++i)
#pragma unroll
        for (int j = 0; j < 4; ++j)
#pragma unroll
            for (int k = 0; k < 4; ++k) acc[i][j][k] = 0.f;

    const int a_r  = (lid & 7) + ((lid >> 3) & 1) * 8;
    const int a_kb = lid >> 4;
    const int b_r  = (lid & 7) + ((lid >> 4) & 1) * 8;
    const int b_kb = (lid >> 3) & 1;

    int ph[STAGES] = {0, 0, 0, 0};

    for (int kt = 0; kt < NCHUNK; ++kt) {
        const int s = kt % STAGES;
        MBAR_WAIT(sb + s * 8, ph[s]);
        ph[s] ^= 1;
        if (tid == 0 && kt + 3 < NCHUNK) issue(kt + 3, (kt + 3) % STAGES);

        const uint32_t st = sb + 1024 + s * STAGE_BYTES;
#pragma unroll
        for (int ks = 0; ks < 4; ++ks) {
            uint32_t af[4][4], bf[2][4];
#pragma unroll
            for (int mt = 0; mt < 4; ++mt) {
                int r = wr * 64 + mt * 16 + a_r;
                int u = ks * 2 + a_kb;
                ldm_x4(af[mt], st + OFF_A + r * 128 + ((u ^ (r & 7)) << 4));
            }
#pragma unroll
            for (int np = 0; np < 2; ++np) {
                int n = wc * 32 + np * 16 + b_r;
                int u = ks * 2 + b_kb;
                ldm_x4(bf[np], st + OFF_B + n * 128 + ((u ^ (n & 7)) << 4));
            }
#pragma unroll
            for (int mt = 0; mt < 4; ++mt)
#pragma unroll
                for (int nt = 0; nt < 4; ++nt) {
                    uint32_t bb[2] = { bf[nt >> 1][(nt & 1) * 2],
                                       bf[nt >> 1][(nt & 1) * 2 + 1] };
                    mma_16816(acc[mt][nt], af[mt], bb);
                }
        }
        __syncthreads();
    }

    // fused epilogue: bias + gate transform + packed half2(a,b) store
    const int g = lid >> 2, tig = lid & 3;
#pragma unroll
    for (int mt = 0; mt < 4; ++mt) {
        int row0 = rowBase + wr * 64 + mt * 16 + g;
#pragma unroll
        for (int nt = 0; nt < 4; ++nt) {
            int p = ((colBase + wc * 32 + nt * 8) >> 1) + tig;
            float bg = bias[p], bh = bias[HID + p];
            float* c = acc[mt][nt];
            ab[(size_t)row0 * HID + p]       = gate2ab(c[0] + bg, c[1] + bh);
            ab[(size_t)(row0 + 8) * HID + p] = gate2ab(c[2] + bg, c[3] + bh);
        }
    }
}

// ---------------------------------------------------------------------------
// fp32 -> fp16 tiled+swizzled. PAIR=true interleaves W rows (gate_p, hid_p).
// ---------------------------------------------------------------------------
template <int TR, bool PAIR>
__global__ void conv_tiled(const float* __restrict__ in,
                           uint4* __restrict__ hi, int nunits) {
    int i = blockIdx.x * blockDim.x + threadIdx.x;
    if (i >= nunits) return;
    int m  = i >> 7;
    int ku = i & 127;
    int kc = ku >> 3, u = ku & 7;
    int dm = PAIR ? (2 * (m & (HID - 1)) + (m >> 10)) : m;
    int mb = dm / TR, r = dm % TR;

    const float4* p = (const float4*)(in + (size_t)m * K_ + ku * 8);
    float4 v0 = p[0], v1 = p[1];
    float vv[8] = {v0.x, v0.y, v0.z, v0.w, v1.x, v1.y, v1.z, v1.w};

    uint32_t hw[4];
#pragma unroll
    for (int j = 0; j < 4; ++j) {
        __half h0 = __float2half_rn(vv[2 * j]);
        __half h1 = __float2half_rn(vv[2 * j + 1]);
        hw[j] = (uint32_t)__half_as_ushort(h0) |
                ((uint32_t)__half_as_ushort(h1) << 16);
    }
    size_t tile = ((size_t)mb * NCHUNK + kc) * (TR * 8);
    hi[tile + r * 8 + (u ^ (r & 7))] = make_uint4(hw[0], hw[1], hw[2], hw[3]);
}

// ---------------------------------------------------------------------------
// Phase 1: per-chunk (A,B) summaries from the fp16 ab plane.
// ---------------------------------------------------------------------------
__global__ void __launch_bounds__(128) scan_sum() {
    const int ch = blockIdx.x * 128 + threadIdx.x;
    const int ck = blockIdx.y;
    const int b = ch >> 10, hid = ch & (HID - 1);
    const size_t rowbase = (size_t)b * S_ + ck * CKS;

    float A = 1.f, Bc = 0.f;
#pragma unroll 8
    for (int s = 0; s < CKS; ++s) {
        uint32_t u = g_ab[(rowbase + s) * HID + hid];
        __half2 h2 = *(__half2*)&u;
        float a = __low2float(h2), bv = __high2float(h2);
        Bc = fmaf(a, Bc, bv);
        A *= a;
    }
    g_sumA[ch * NCK + ck] = A;
    g_sumB[ch * NCK + ck] = Bc;
}

// ---------------------------------------------------------------------------
// Phase 2: per-channel warp scan over 32 chunk summaries.
// ---------------------------------------------------------------------------
__global__ void __launch_bounds__(256) scan_phase2(const float* __restrict__ h0) {
    const int gt = blockIdx.x * 256 + threadIdx.x;
    const int ch = gt >> 5;
    const int lane = gt & 31;

    float A = g_sumA[ch * NCK + lane];
    float Bv = g_sumB[ch * NCK + lane];
#pragma unroll
    for (int off = 1; off < 32; off <<= 1) {
        float pA = __shfl_up_sync(0xFFFFFFFF, A, off);
        float pB = __shfl_up_sync(0xFFFFFFFF, Bv, off);
        if (lane >= off) {
            Bv = fmaf(A, pB, Bv);
            A  = pA * A;
        }
    }
    float eA = __shfl_up_sync(0xFFFFFFFF, A, 1);
    float eB = __shfl_up_sync(0xFFFFFFFF, Bv, 1);
    if (lane == 0) { eA = 1.f; eB = 0.f; }

    float x = h0[ch];
    float h0g = (x >= 0.f) ? (x + 0.5f)
                           : __fdividef(__expf(x), 1.f + __expf(x));
    g_start[lane * CH_ + ch] = fmaf(eA, h0g, eB);
}

// ---------------------------------------------------------------------------
// Phase 3: 8 channels/thread local scan + residual; optionally emits
// next layer's tiled fp16 A in-line. grid (8, 32) x 128.
// ---------------------------------------------------------------------------
template <bool EMIT_A>
__global__ void __launch_bounds__(128)
scan_phase3(const float* __restrict__ resid, float* __restrict__ outp,
            float* __restrict__ finals) {
    const int cg = blockIdx.x * 128 + threadIdx.x;   // 0..1023 channel groups
    const int ck = blockIdx.y;
    const int b = cg >> 7;
    const int ku = cg & 127;                          // hid unit (8 ch)
    const int hid0 = ku * 8;
    const int ch0 = b * HID + hid0;
    const size_t rowbase = (size_t)b * S_ + ck * CKS;
    const int kc = ku >> 3, uu = ku & 7;

    float h[8];
    {
        const float4* sp = (const float4*)(g_start + ck * CH_ + ch0);
        float4 s0 = sp[0], s1 = sp[1];
        h[0] = s0.x; h[1] = s0.y; h[2] = s0.z; h[3] = s0.w;
        h[4] = s1.x; h[5] = s1.y; h[6] = s1.z; h[7] = s1.w;
    }

#pragma unroll 4
    for (int s = 0; s < CKS; ++s) {
        size_t row = rowbase + s;
        const uint4* abp = (const uint4*)(g_ab + row * HID + hid0);
        uint4 u0 = abp[0], u1 = abp[1];
        const float4* rp = (const float4*)(resid + row * HID + hid0);
        float4 r0 = rp[0], r1 = rp[1];

        uint32_t uw[8] = {u0.x, u0.y, u0.z, u0.w, u1.x, u1.y, u1.z, u1.w};
        float rr[8] = {r0.x, r0.y, r0.z, r0.w, r1.x, r1.y, r1.z, r1.w};
        float ov[8];
#pragma unroll
        for (int j = 0; j < 8; ++j) {
            __half2 h2 = *(__half2*)&uw[j];
            h[j] = fmaf(__low2float(h2), h[j], __high2float(h2));
            ov[j] = h[j] + rr[j];
        }
        float4* op = (float4*)(outp + row * HID + hid0);
        op[0] = make_float4(ov[0], ov[1], ov[2], ov[3]);
        op[1] = make_float4(ov[4], ov[5], ov[6], ov[7]);

        if (EMIT_A) {
            uint32_t hw[4];
#pragma unroll
            for (int j = 0; j < 4; ++j) {
                __half a0 = __float2half_rn(ov[2 * j]);
                __half a1 = __float2half_rn(ov[2 * j + 1]);
                hw[j] = (uint32_t)__half_as_ushort(a0) |
                        ((uint32_t)__half_as_ushort(a1) << 16);
            }
            int mb = (int)(row >> 7), r = (int)(row & 127);
            g_Ah[((size_t)mb * NCHUNK + kc) * 1024 + r * 8 + (uu ^ (r & 7))] =
                make_uint4(hw[0], hw[1], hw[2], hw[3]);
        }
    }

    if (ck == NCK - 1) {
        float4* fp = (float4*)(finals + ch0);
        fp[0] = make_float4(h[0], h[1], h[2], h[3]);
        fp[1] = make_float4(h[4], h[5], h[6], h[7]);
    }
}

// ---------------------------------------------------------------------------
// Launcher
// ---------------------------------------------------------------------------
extern "C" void kernel_launch(void* const* d_in, const int* in_sizes, int n_in,
                              void* d_out, int out_size) {
    const float* x  = (const float*)d_in[0];
    const float* h  = (const float*)d_in[1];
    const float* W0 = (const float*)d_in[2];
    const float* b0 = (const float*)d_in[3];
    const float* Wl = (const float*)d_in[4];
    const float* bl = (const float*)d_in[5];

    float* out    = (float*)d_out;
    float* finals = out + (size_t)M_ * HID;

    float* inp;
    uint32_t* ab;
    uint4 *Ah, *Wh;
    cudaGetSymbolAddress((void**)&inp, g_inp);
    cudaGetSymbolAddress((void**)&ab,  g_ab);
    cudaGetSymbolAddress((void**)&Ah,  g_Ah);
    cudaGetSymbolAddress((void**)&Wh,  g_Wh);

    cudaFuncSetAttribute(gemm_mma, cudaFuncAttributeMaxDynamicSharedMemorySize,
                         SMEM_BYTES);

    const int nAu = M_ * K_ / 8;
    const int nWu = N_ * K_ / 8;
    dim3 ggrid(N_ / BN, M_ / BM);     // (8, 128)
    dim3 sgrid(CH_ / 128, NCK);       // (64, 32)
    dim3 pgrid(8, NCK);               // phase3: 1024 groups / 128

    for (int l = 0; l < L_; ++l) {
        const float* W = (l == 0) ? W0 : (Wl + (size_t)(l - 1) * N_ * K_);
        const float* b = (l == 0) ? b0 : (bl + (size_t)(l - 1) * N_);
        const float* src = (l == 0) ? x : inp;

        if (l == 0)
            conv_tiled<BM, false><<<(nAu + 255) / 256, 256>>>(x, Ah, nAu);
        conv_tiled<BN, true><<<(nWu + 255) / 256, 256>>>(W, Wh, nWu);
        gemm_mma<<<ggrid, GTHREADS, SMEM_BYTES>>>((const char*)Ah,
                                                  (const char*)Wh, b, ab);

        scan_sum<<<sgrid, 128>>>();
        scan_phase2<<<CH_ * 32 / 256, 256>>>(h + (size_t)l * CH_);
        float* ob = (l == L_ - 1) ? out : inp;
        if (l == L_ - 1)
            scan_phase3<false><<<pgrid, 128>>>(src, ob,
                                               finals + (size_t)l * CH_);
        else
            scan_phase3<true><<<pgrid, 128>>>(src, ob,
                                              finals + (size_t)l * CH_);
    }
}